// round 1
// baseline (speedup 1.0000x reference)
#include <cuda_runtime.h>
#include <math.h>

// Problem constants (fixed by the reference)
#define BATCH   8
#define SEQ     4096
#define DMODEL  1024
#define DSTATE  64
#define NPROJ   320          // D_STATE + 2*INNER = 64 + 256
#define NCHUNK  64
#define CLEN    64           // SEQ / NCHUNK
#define M_ROWS  (BATCH*SEQ)  // 32768

// ---------------------------------------------------------------------------
// Scratch (static __device__ globals; no allocation in kernel_launch)
// ---------------------------------------------------------------------------
__device__ float g_xc  [(size_t)M_ROWS * DMODEL];   // conv output, 134 MB
__device__ float g_proj[(size_t)M_ROWS * NPROJ];    // in_proj output, 42 MB
__device__ float g_Abar[(size_t)M_ROWS * DSTATE];   // 8 MB each
__device__ float g_Bbar[(size_t)M_ROWS * DSTATE];
__device__ float g_Cm  [(size_t)M_ROWS * DSTATE];
__device__ float g_y   [(size_t)M_ROWS * DSTATE];
__device__ float g_P   [BATCH * NCHUNK * DSTATE];
__device__ float g_H   [BATCH * NCHUNK * DSTATE];
__device__ float g_Hin [BATCH * NCHUNK * DSTATE];

// ---------------------------------------------------------------------------
// 1. Depthwise causal-ish conv (k=4, pad=(1,1)), last timestep zeroed.
//    xc[b,t,d] = cb[d] + sum_j cw[d,j] * x[b, t-1+j, d]   for t < SEQ-1
//    xc[b,SEQ-1,d] = 0   (reference pads conv output of length L-1 with zeros)
// ---------------------------------------------------------------------------
__global__ void conv_kernel(const float* __restrict__ x,
                            const float* __restrict__ cw,
                            const float* __restrict__ cb)
{
    const int D4  = DMODEL / 4;
    int idx = blockIdx.x * blockDim.x + threadIdx.x;
    if (idx >= BATCH * SEQ * D4) return;

    int d4 = idx % D4;
    int bt = idx / D4;
    int t  = bt % SEQ;
    int b  = bt / SEQ;
    int d  = d4 * 4;

    float4* outp = (float4*)(g_xc + (size_t)bt * DMODEL + d);
    if (t == SEQ - 1) { *outp = make_float4(0.f, 0.f, 0.f, 0.f); return; }

    float4 acc = *(const float4*)(cb + d);
    float4 w0 = *(const float4*)(cw + (size_t)(d + 0) * 4);
    float4 w1 = *(const float4*)(cw + (size_t)(d + 1) * 4);
    float4 w2 = *(const float4*)(cw + (size_t)(d + 2) * 4);
    float4 w3 = *(const float4*)(cw + (size_t)(d + 3) * 4);
    const float* wa0 = (const float*)&w0;
    const float* wa1 = (const float*)&w1;
    const float* wa2 = (const float*)&w2;
    const float* wa3 = (const float*)&w3;

    const float* xb = x + (size_t)b * SEQ * DMODEL + d;
    #pragma unroll
    for (int j = 0; j < 4; j++) {
        int tt = t - 1 + j;
        if (tt < 0 || tt >= SEQ) continue;
        float4 xv = *(const float4*)(xb + (size_t)tt * DMODEL);
        acc.x = fmaf(wa0[j], xv.x, acc.x);
        acc.y = fmaf(wa1[j], xv.y, acc.y);
        acc.z = fmaf(wa2[j], xv.z, acc.z);
        acc.w = fmaf(wa3[j], xv.w, acc.w);
    }
    *outp = acc;
}

// ---------------------------------------------------------------------------
// 2. Register-tiled fp32 SGEMM:  C[M,N] = A[M,K] @ W[N,K]^T + bias[N]
//    Both A and W are K-major (row-major with K contiguous).
//    Fixed config: BM=128, BN=64, BK=16, TM=8, TN=4, 256 threads.
// ---------------------------------------------------------------------------
__global__ __launch_bounds__(256)
void sgemm_tn(int M, int N, int K,
              const float* __restrict__ A,
              const float* __restrict__ W,
              const float* __restrict__ bias,
              float* __restrict__ C)
{
    const int BM = 128, BN = 64, BK = 16, TM = 8, TN = 4;
    __shared__ float As[BK][BM + 4];
    __shared__ float Ws[BK][BN + 4];

    const int tid = threadIdx.x;
    const int bm  = blockIdx.y * BM;
    const int bn  = blockIdx.x * BN;
    const int tx  = tid % (BN / TN);   // 0..15  (n direction)
    const int ty  = tid / (BN / TN);   // 0..15  (m direction)

    // vectorized tile-load mapping: each thread loads float4 at (vrow, vcol)
    const int vrow = tid / (BK / 4);          // 0..63
    const int vcol = (tid % (BK / 4)) * 4;    // 0,4,8,12

    float acc[TM][TN];
    #pragma unroll
    for (int i = 0; i < TM; i++)
        #pragma unroll
        for (int j = 0; j < TN; j++) acc[i][j] = 0.f;

    for (int k0 = 0; k0 < K; k0 += BK) {
        // A tile: 128 rows x 16 cols, two passes of 64 rows
        #pragma unroll
        for (int r = 0; r < BM; r += 64) {
            float4 v = *(const float4*)(A + (size_t)(bm + vrow + r) * K + (k0 + vcol));
            As[vcol + 0][vrow + r] = v.x;
            As[vcol + 1][vrow + r] = v.y;
            As[vcol + 2][vrow + r] = v.z;
            As[vcol + 3][vrow + r] = v.w;
        }
        // W tile: 64 rows x 16 cols, one pass
        {
            float4 v = *(const float4*)(W + (size_t)(bn + vrow) * K + (k0 + vcol));
            Ws[vcol + 0][vrow] = v.x;
            Ws[vcol + 1][vrow] = v.y;
            Ws[vcol + 2][vrow] = v.z;
            Ws[vcol + 3][vrow] = v.w;
        }
        __syncthreads();

        #pragma unroll
        for (int kk = 0; kk < BK; kk++) {
            float a[TM], w[TN];
            #pragma unroll
            for (int i = 0; i < TM; i++) a[i] = As[kk][ty * TM + i];
            #pragma unroll
            for (int j = 0; j < TN; j++) w[j] = Ws[kk][tx * TN + j];
            #pragma unroll
            for (int i = 0; i < TM; i++)
                #pragma unroll
                for (int j = 0; j < TN; j++)
                    acc[i][j] = fmaf(a[i], w[j], acc[i][j]);
        }
        __syncthreads();
    }

    float4 bv = *(const float4*)(bias + bn + tx * TN);
    #pragma unroll
    for (int i = 0; i < TM; i++) {
        int m = bm + ty * TM + i;
        float4 o;
        o.x = acc[i][0] + bv.x;
        o.y = acc[i][1] + bv.y;
        o.z = acc[i][2] + bv.z;
        o.w = acc[i][3] + bv.w;
        *(float4*)(C + (size_t)m * N + bn + tx * TN) = o;
    }
}

// ---------------------------------------------------------------------------
// 3. Elementwise: split proj -> delta / B(pair-mean) / C(pair-mean),
//    softplus, A_bar = exp(delta*A), B_bar = scale * B_mean.
// ---------------------------------------------------------------------------
__global__ void elem_kernel(const float* __restrict__ Alog)
{
    int idx = blockIdx.x * blockDim.x + threadIdx.x;
    if (idx >= M_ROWS * DSTATE) return;
    int s  = idx % DSTATE;
    int bt = idx / DSTATE;

    const float* p = g_proj + (size_t)bt * NPROJ;
    float  delta = p[s];
    float2 bv = *(const float2*)(p + DSTATE + 2 * s);
    float2 cv = *(const float2*)(p + DSTATE + 2 * DSTATE + 2 * DSTATE + 2 * s); // 64+128+... see below
    // NPROJ layout: [0,64) delta | [64,192) B (64 pairs) | [192,320) C (64 pairs)
    bv = *(const float2*)(p + 64  + 2 * s);
    cv = *(const float2*)(p + 192 + 2 * s);

    float Bm = 0.5f * (bv.x + bv.y);
    float Cm = 0.5f * (cv.x + cv.y);

    float A  = -__expf(0.f) ; // placeholder avoided; use precise expf below
    A = -expf(Alog[s]);

    // softplus = max(x,0) + log1p(exp(-|x|))
    float sp = fmaxf(delta, 0.f) + log1pf(expf(-fabsf(delta)));
    float dA = sp * A;
    float Abar = expf(dA);

    float scale;
    if (fabsf(A) < 1e-4f) {
        scale = 1.f + dA * 0.5f + dA * dA * (1.f / 6.f);
    } else {
        scale = (Abar - 1.f) / A;
    }

    g_Abar[idx] = Abar;
    g_Bbar[idx] = scale * Bm;
    g_Cm[idx]   = Cm;
}

// ---------------------------------------------------------------------------
// 4. Chunked linear-recurrence scan: h[t] = A_bar[t]*h[t-1] + B_bar[t]
//    Pass A: per-chunk local scan -> (prod A, local h end)
//    Pass B: sequential scan over chunks -> carry-in per chunk
//    Pass C: redo local scan with carry-in, write y = C * h
// ---------------------------------------------------------------------------
__global__ void scanA_kernel()
{
    int b = blockIdx.x / NCHUNK;
    int c = blockIdx.x % NCHUNK;
    int s = threadIdx.x;
    size_t base = ((size_t)b * SEQ + (size_t)c * CLEN) * DSTATE + s;
    float h = 0.f, p = 1.f;
    #pragma unroll 4
    for (int i = 0; i < CLEN; i++) {
        float a  = g_Abar[base + (size_t)i * DSTATE];
        float bb = g_Bbar[base + (size_t)i * DSTATE];
        h = fmaf(a, h, bb);
        p *= a;
    }
    int o = (b * NCHUNK + c) * DSTATE + s;
    g_P[o] = p;
    g_H[o] = h;
}

__global__ void scanB_kernel()
{
    int b = blockIdx.x;
    int s = threadIdx.x;
    int base = b * NCHUNK * DSTATE + s;
    float h  = 0.f;
    float pc = g_P[base];
    float hc = g_H[base];
    for (int c = 0; c < NCHUNK; c++) {
        float pn = 0.f, hn = 0.f;
        if (c + 1 < NCHUNK) {
            pn = g_P[base + (c + 1) * DSTATE];
            hn = g_H[base + (c + 1) * DSTATE];
        }
        g_Hin[base + c * DSTATE] = h;
        h  = fmaf(pc, h, hc);
        pc = pn; hc = hn;
    }
}

__global__ void scanC_kernel()
{
    int b = blockIdx.x / NCHUNK;
    int c = blockIdx.x % NCHUNK;
    int s = threadIdx.x;
    float h = g_Hin[(b * NCHUNK + c) * DSTATE + s];
    size_t base = ((size_t)b * SEQ + (size_t)c * CLEN) * DSTATE + s;
    #pragma unroll 4
    for (int i = 0; i < CLEN; i++) {
        float a  = g_Abar[base + (size_t)i * DSTATE];
        float bb = g_Bbar[base + (size_t)i * DSTATE];
        h = fmaf(a, h, bb);
        g_y[base + (size_t)i * DSTATE] = g_Cm[base + (size_t)i * DSTATE] * h;
    }
}

// ---------------------------------------------------------------------------
// Launch
// ---------------------------------------------------------------------------
extern "C" void kernel_launch(void* const* d_in, const int* in_sizes, int n_in,
                              void* d_out, int out_size)
{
    (void)in_sizes; (void)n_in; (void)out_size;
    const float* x    = (const float*)d_in[0];
    const float* cw   = (const float*)d_in[1];
    const float* cb   = (const float*)d_in[2];
    const float* w1   = (const float*)d_in[3];
    const float* b1   = (const float*)d_in[4];
    const float* alog = (const float*)d_in[5];
    const float* w2   = (const float*)d_in[6];
    const float* b2   = (const float*)d_in[7];
    float* out = (float*)d_out;

    float *xc_p, *proj_p, *y_p;
    cudaGetSymbolAddress((void**)&xc_p,   g_xc);
    cudaGetSymbolAddress((void**)&proj_p, g_proj);
    cudaGetSymbolAddress((void**)&y_p,    g_y);

    // 1. conv
    {
        int n = BATCH * SEQ * (DMODEL / 4);
        conv_kernel<<<(n + 255) / 256, 256>>>(x, cw, cb);
    }
    // 2. proj = xc @ W1^T + b1   (M=32768, N=320, K=1024)
    {
        dim3 grid(NPROJ / 64, M_ROWS / 128);
        sgemm_tn<<<grid, 256>>>(M_ROWS, NPROJ, DMODEL, xc_p, w1, b1, proj_p);
    }
    // 3. elementwise SSM params
    {
        int n = M_ROWS * DSTATE;
        elem_kernel<<<(n + 255) / 256, 256>>>(alog);
    }
    // 4. chunked scan
    scanA_kernel<<<BATCH * NCHUNK, DSTATE>>>();
    scanB_kernel<<<BATCH, DSTATE>>>();
    scanC_kernel<<<BATCH * NCHUNK, DSTATE>>>();

    // 5. out = y @ W2^T + b2   (M=32768, N=1024, K=64)
    {
        dim3 grid(DMODEL / 64, M_ROWS / 128);
        sgemm_tn<<<grid, 256>>>(M_ROWS, DMODEL, DSTATE, y_p, w2, b2, out);
    }
}

// round 3
// speedup vs baseline: 1.7660x; 1.7660x over previous
#include <cuda_runtime.h>
#include <cuda_bf16.h>
#include <math.h>
#include <stdint.h>

// Problem constants (fixed by the reference)
#define BATCH   8
#define SEQ     4096
#define DMODEL  1024
#define DSTATE  64
#define NPROJ   320          // D_STATE + 2*INNER = 64 + 256
#define NCHUNK  64
#define CLEN    64           // SEQ / NCHUNK
#define M_ROWS  (BATCH*SEQ)  // 32768

// ---------------------------------------------------------------------------
// Scratch (static __device__ globals; no allocation in kernel_launch)
// ---------------------------------------------------------------------------
__device__ __nv_bfloat16 g_xch[(size_t)M_ROWS * DMODEL];  // conv out, hi bf16
__device__ __nv_bfloat16 g_xcl[(size_t)M_ROWS * DMODEL];  // conv out, lo bf16
__device__ __nv_bfloat16 g_w1h[(size_t)NPROJ * DMODEL];
__device__ __nv_bfloat16 g_w1l[(size_t)NPROJ * DMODEL];
__device__ __nv_bfloat16 g_w2h[(size_t)DMODEL * DSTATE];
__device__ __nv_bfloat16 g_w2l[(size_t)DMODEL * DSTATE];
__device__ __nv_bfloat16 g_yh [(size_t)M_ROWS * DSTATE];
__device__ __nv_bfloat16 g_yl [(size_t)M_ROWS * DSTATE];
__device__ float g_proj[(size_t)M_ROWS * NPROJ];    // in_proj output, 42 MB
__device__ float g_Abar[(size_t)M_ROWS * DSTATE];
__device__ float g_Bbar[(size_t)M_ROWS * DSTATE];
__device__ float g_Cm  [(size_t)M_ROWS * DSTATE];
__device__ float g_P   [BATCH * NCHUNK * DSTATE];
__device__ float g_H   [BATCH * NCHUNK * DSTATE];
__device__ float g_Hin [BATCH * NCHUNK * DSTATE];

// ---------------------------------------------------------------------------
// PTX helpers (legacy tensor path: ldmatrix + mma.sync, valid on sm_100 base)
// ---------------------------------------------------------------------------
__device__ __forceinline__ uint32_t smem_u32(const void* p) {
    uint32_t a;
    asm("{ .reg .u64 t; cvta.to.shared.u64 t, %1; cvt.u32.u64 %0, t; }" : "=r"(a) : "l"(p));
    return a;
}
__device__ __forceinline__ void ldsm_x4(uint32_t* r, uint32_t addr) {
    asm volatile("ldmatrix.sync.aligned.m8n8.x4.shared.b16 {%0,%1,%2,%3}, [%4];"
        : "=r"(r[0]), "=r"(r[1]), "=r"(r[2]), "=r"(r[3]) : "r"(addr));
}
__device__ __forceinline__ void ldsm_x2(uint32_t* r, uint32_t addr) {
    asm volatile("ldmatrix.sync.aligned.m8n8.x2.shared.b16 {%0,%1}, [%2];"
        : "=r"(r[0]), "=r"(r[1]) : "r"(addr));
}
__device__ __forceinline__ void mma_bf16(float* d, const uint32_t* a, const uint32_t* b) {
    asm volatile("mma.sync.aligned.m16n8k16.row.col.f32.bf16.bf16.f32 "
        "{%0,%1,%2,%3}, {%4,%5,%6,%7}, {%8,%9}, {%0,%1,%2,%3};"
        : "+f"(d[0]), "+f"(d[1]), "+f"(d[2]), "+f"(d[3])
        : "r"(a[0]), "r"(a[1]), "r"(a[2]), "r"(a[3]), "r"(b[0]), "r"(b[1]));
}
__device__ __forceinline__ void cp16(uint32_t saddr, const void* gaddr) {
    asm volatile("cp.async.cg.shared.global [%0], [%1], 16;" :: "r"(saddr), "l"(gaddr) : "memory");
}
__device__ __forceinline__ void cp_commit_wait() {
    asm volatile("cp.async.commit_group;" ::: "memory");
    asm volatile("cp.async.wait_group 0;" ::: "memory");
}
// SW128 swizzle on byte offsets (rows of 128 bytes)
#define SWZ(off) ((uint32_t)(off) ^ ((((uint32_t)(off)) >> 3) & 0x70))

// ---------------------------------------------------------------------------
// 1. Depthwise conv (k=4, pad=(1,1)), last timestep zeroed.
//    Emits split-bf16 (hi, lo) directly for the tensor-core GEMM.
// ---------------------------------------------------------------------------
__global__ void conv_kernel(const float* __restrict__ x,
                            const float* __restrict__ cw,
                            const float* __restrict__ cb)
{
    const int D4  = DMODEL / 4;
    int idx = blockIdx.x * blockDim.x + threadIdx.x;
    if (idx >= BATCH * SEQ * D4) return;

    int d4 = idx % D4;
    int bt = idx / D4;
    int t  = bt % SEQ;
    int b  = bt / SEQ;
    int d  = d4 * 4;

    float4 acc;
    if (t == SEQ - 1) {
        acc = make_float4(0.f, 0.f, 0.f, 0.f);
    } else {
        acc = *(const float4*)(cb + d);
        float4 w0 = *(const float4*)(cw + (size_t)(d + 0) * 4);
        float4 w1 = *(const float4*)(cw + (size_t)(d + 1) * 4);
        float4 w2 = *(const float4*)(cw + (size_t)(d + 2) * 4);
        float4 w3 = *(const float4*)(cw + (size_t)(d + 3) * 4);
        const float* wa0 = (const float*)&w0;
        const float* wa1 = (const float*)&w1;
        const float* wa2 = (const float*)&w2;
        const float* wa3 = (const float*)&w3;
        const float* xb = x + (size_t)b * SEQ * DMODEL + d;
        #pragma unroll
        for (int j = 0; j < 4; j++) {
            int tt = t - 1 + j;
            if (tt < 0 || tt >= SEQ) continue;
            float4 xv = *(const float4*)(xb + (size_t)tt * DMODEL);
            acc.x = fmaf(wa0[j], xv.x, acc.x);
            acc.y = fmaf(wa1[j], xv.y, acc.y);
            acc.z = fmaf(wa2[j], xv.z, acc.z);
            acc.w = fmaf(wa3[j], xv.w, acc.w);
        }
    }
    const float* a = (const float*)&acc;
    __nv_bfloat16 hi[4], lo[4];
    #pragma unroll
    for (int j = 0; j < 4; j++) {
        hi[j] = __float2bfloat16(a[j]);
        lo[j] = __float2bfloat16(a[j] - __bfloat162float(hi[j]));
    }
    size_t off = (size_t)bt * DMODEL + d;
    *(uint2*)(g_xch + off) = *(const uint2*)hi;
    *(uint2*)(g_xcl + off) = *(const uint2*)lo;
}

// ---------------------------------------------------------------------------
// 1b. Split weights into bf16 hi/lo
// ---------------------------------------------------------------------------
__global__ void wsplit_kernel(const float* __restrict__ w,
                              __nv_bfloat16* __restrict__ oh,
                              __nv_bfloat16* __restrict__ ol, int n)
{
    int i = blockIdx.x * blockDim.x + threadIdx.x;
    if (i >= n) return;
    float v = w[i];
    __nv_bfloat16 hi = __float2bfloat16(v);
    oh[i] = hi;
    ol[i] = __float2bfloat16(v - __bfloat162float(hi));
}

// ---------------------------------------------------------------------------
// 2. GEMM1 via mma.sync (split bf16, 3 passes):
//    proj[M,320] = xc[M,1024] @ W1[320,1024]^T + b1
//    CTA tile 128x160, K chunks of 64. 8 warps (2m x 4n), warp tile 64x40.
// ---------------------------------------------------------------------------
#define G1_AH 0
#define G1_AL 16384
#define G1_BH 32768
#define G1_BL 53248
#define G1_SMEM 73728

__global__ __launch_bounds__(256)
void gemm1_mma(const float* __restrict__ bias)
{
    extern __shared__ char smem[];
    const uint32_t sb = smem_u32(smem);
    const int tid  = threadIdx.x;
    const int lane = tid & 31;
    const int wid  = tid >> 5;
    const int wm   = (wid >> 2) * 64;   // 0 / 64
    const int wn   = (wid & 3) * 40;    // 0..120
    const int bm   = blockIdx.y * 128;
    const int bn   = blockIdx.x * 160;

    float d[4][5][4];
    #pragma unroll
    for (int i = 0; i < 4; i++)
        #pragma unroll
        for (int j = 0; j < 5; j++)
            #pragma unroll
            for (int c = 0; c < 4; c++) d[i][j][c] = 0.f;

    for (int iter = 0; iter < 16; iter++) {
        const int k0 = iter * 64;
        // A tiles: 128 rows x 128B, hi + lo
        #pragma unroll
        for (int i = tid; i < 1024; i += 256) {
            int r = i >> 3, cB = (i & 7) << 4;
            size_t go = (size_t)(bm + r) * DMODEL + k0 + (cB >> 1);
            uint32_t so = SWZ(r * 128 + cB);
            cp16(sb + G1_AH + so, g_xch + go);
            cp16(sb + G1_AL + so, g_xcl + go);
        }
        // B tiles: 160 rows x 128B, hi + lo
        #pragma unroll
        for (int i = tid; i < 1280; i += 256) {
            int r = i >> 3, cB = (i & 7) << 4;
            size_t go = (size_t)(bn + r) * DMODEL + k0 + (cB >> 1);
            uint32_t so = SWZ(r * 128 + cB);
            cp16(sb + G1_BH + so, g_w1h + go);
            cp16(sb + G1_BL + so, g_w1l + go);
        }
        cp_commit_wait();
        __syncthreads();

        #pragma unroll
        for (int ks = 0; ks < 4; ks++) {
            const int kb = ks * 32;     // byte col of this k16 step
            // B fragments (5 n8 atoms), hi and lo
            uint32_t bh[5][2], bl[5][2];
            {
                int mi  = lane >> 3;
                int row = wn + ((mi & 1) << 3) + (lane & 7);
                int col = kb + ((mi >> 1) << 4);
                uint32_t so = SWZ(row * 128 + col);
                uint32_t r4[4];
                ldsm_x4(r4, sb + G1_BH + so);
                bh[0][0] = r4[0]; bh[1][0] = r4[1]; bh[0][1] = r4[2]; bh[1][1] = r4[3];
                ldsm_x4(r4, sb + G1_BL + so);
                bl[0][0] = r4[0]; bl[1][0] = r4[1]; bl[0][1] = r4[2]; bl[1][1] = r4[3];

                uint32_t so2 = SWZ((row + 16) * 128 + col);
                ldsm_x4(r4, sb + G1_BH + so2);
                bh[2][0] = r4[0]; bh[3][0] = r4[1]; bh[2][1] = r4[2]; bh[3][1] = r4[3];
                ldsm_x4(r4, sb + G1_BL + so2);
                bl[2][0] = r4[0]; bl[3][0] = r4[1]; bl[2][1] = r4[2]; bl[3][1] = r4[3];
            }
            {
                int mi  = (lane >> 3) & 1;
                int row = wn + 32 + (lane & 7);
                int col = kb + (mi << 4);
                uint32_t so = SWZ(row * 128 + col);
                ldsm_x2(bh[4], sb + G1_BH + so);
                ldsm_x2(bl[4], sb + G1_BL + so);
            }
            // A atoms (4 m16), hi and lo; 3-pass accumulate
            #pragma unroll
            for (int i = 0; i < 4; i++) {
                int mi  = lane >> 3;
                int row = wm + i * 16 + ((mi & 1) << 3) + (lane & 7);
                int col = kb + ((mi >> 1) << 4);
                uint32_t so = SWZ(row * 128 + col);
                uint32_t ah[4], al[4];
                ldsm_x4(ah, sb + G1_AH + so);
                ldsm_x4(al, sb + G1_AL + so);
                #pragma unroll
                for (int j = 0; j < 5; j++) {
                    mma_bf16(d[i][j], ah, bh[j]);
                    mma_bf16(d[i][j], ah, bl[j]);
                    mma_bf16(d[i][j], al, bh[j]);
                }
            }
        }
        __syncthreads();
    }

    // Epilogue
    const int gid = lane >> 2, tig = lane & 3;
    #pragma unroll
    for (int i = 0; i < 4; i++) {
        int row0 = bm + wm + i * 16 + gid;
        #pragma unroll
        for (int j = 0; j < 5; j++) {
            int col = bn + wn + j * 8 + tig * 2;
            float b0 = bias[col], b1 = bias[col + 1];
            float2 v0 = make_float2(d[i][j][0] + b0, d[i][j][1] + b1);
            float2 v1 = make_float2(d[i][j][2] + b0, d[i][j][3] + b1);
            *(float2*)(g_proj + (size_t)row0 * NPROJ + col)       = v0;
            *(float2*)(g_proj + (size_t)(row0 + 8) * NPROJ + col) = v1;
        }
    }
}

// ---------------------------------------------------------------------------
// 2b. GEMM2 via mma.sync (split bf16, 3 passes):
//    out[M,1024] = y[M,64] @ W2[1024,64]^T + b2
//    CTA tile 128x128, K=64 in one shot. 8 warps (2m x 4n), warp tile 64x32.
// ---------------------------------------------------------------------------
#define G2_AH 0
#define G2_AL 16384
#define G2_BH 32768
#define G2_BL 49152
#define G2_SMEM 65536

__global__ __launch_bounds__(256)
void gemm2_mma(const float* __restrict__ bias, float* __restrict__ out)
{
    extern __shared__ char smem[];
    const uint32_t sb = smem_u32(smem);
    const int tid  = threadIdx.x;
    const int lane = tid & 31;
    const int wid  = tid >> 5;
    const int wm   = (wid >> 2) * 64;
    const int wn   = (wid & 3) * 32;
    const int bm   = blockIdx.y * 128;
    const int bn   = blockIdx.x * 128;

    float d[4][4][4];
    #pragma unroll
    for (int i = 0; i < 4; i++)
        #pragma unroll
        for (int j = 0; j < 4; j++)
            #pragma unroll
            for (int c = 0; c < 4; c++) d[i][j][c] = 0.f;

    // A tile: 128 rows x 128B (64 bf16), hi + lo
    #pragma unroll
    for (int i = tid; i < 1024; i += 256) {
        int r = i >> 3, cB = (i & 7) << 4;
        size_t go = (size_t)(bm + r) * DSTATE + (cB >> 1);
        uint32_t so = SWZ(r * 128 + cB);
        cp16(sb + G2_AH + so, g_yh + go);
        cp16(sb + G2_AL + so, g_yl + go);
    }
    // B tile: 128 rows x 128B
    #pragma unroll
    for (int i = tid; i < 1024; i += 256) {
        int r = i >> 3, cB = (i & 7) << 4;
        size_t go = (size_t)(bn + r) * DSTATE + (cB >> 1);
        uint32_t so = SWZ(r * 128 + cB);
        cp16(sb + G2_BH + so, g_w2h + go);
        cp16(sb + G2_BL + so, g_w2l + go);
    }
    cp_commit_wait();
    __syncthreads();

    #pragma unroll
    for (int ks = 0; ks < 4; ks++) {
        const int kb = ks * 32;
        uint32_t bh[4][2], bl[4][2];
        {
            int mi  = lane >> 3;
            int row = wn + ((mi & 1) << 3) + (lane & 7);
            int col = kb + ((mi >> 1) << 4);
            uint32_t so = SWZ(row * 128 + col);
            uint32_t r4[4];
            ldsm_x4(r4, sb + G2_BH + so);
            bh[0][0] = r4[0]; bh[1][0] = r4[1]; bh[0][1] = r4[2]; bh[1][1] = r4[3];
            ldsm_x4(r4, sb + G2_BL + so);
            bl[0][0] = r4[0]; bl[1][0] = r4[1]; bl[0][1] = r4[2]; bl[1][1] = r4[3];
            uint32_t so2 = SWZ((row + 16) * 128 + col);
            ldsm_x4(r4, sb + G2_BH + so2);
            bh[2][0] = r4[0]; bh[3][0] = r4[1]; bh[2][1] = r4[2]; bh[3][1] = r4[3];
            ldsm_x4(r4, sb + G2_BL + so2);
            bl[2][0] = r4[0]; bl[3][0] = r4[1]; bl[2][1] = r4[2]; bl[3][1] = r4[3];
        }
        #pragma unroll
        for (int i = 0; i < 4; i++) {
            int mi  = lane >> 3;
            int row = wm + i * 16 + ((mi & 1) << 3) + (lane & 7);
            int col = kb + ((mi >> 1) << 4);
            uint32_t so = SWZ(row * 128 + col);
            uint32_t ah[4], al[4];
            ldsm_x4(ah, sb + G2_AH + so);
            ldsm_x4(al, sb + G2_AL + so);
            #pragma unroll
            for (int j = 0; j < 4; j++) {
                mma_bf16(d[i][j], ah, bh[j]);
                mma_bf16(d[i][j], ah, bl[j]);
                mma_bf16(d[i][j], al, bh[j]);
            }
        }
    }

    const int gid = lane >> 2, tig = lane & 3;
    #pragma unroll
    for (int i = 0; i < 4; i++) {
        int row0 = bm + wm + i * 16 + gid;
        #pragma unroll
        for (int j = 0; j < 4; j++) {
            int col = bn + wn + j * 8 + tig * 2;
            float b0 = bias[col], b1 = bias[col + 1];
            float2 v0 = make_float2(d[i][j][0] + b0, d[i][j][1] + b1);
            float2 v1 = make_float2(d[i][j][2] + b0, d[i][j][3] + b1);
            *(float2*)(out + (size_t)row0 * DMODEL + col)       = v0;
            *(float2*)(out + (size_t)(row0 + 8) * DMODEL + col) = v1;
        }
    }
}

// ---------------------------------------------------------------------------
// 3. Elementwise SSM params
// ---------------------------------------------------------------------------
__global__ void elem_kernel(const float* __restrict__ Alog)
{
    int idx = blockIdx.x * blockDim.x + threadIdx.x;
    if (idx >= M_ROWS * DSTATE) return;
    int s  = idx % DSTATE;
    int bt = idx / DSTATE;

    const float* p = g_proj + (size_t)bt * NPROJ;
    float  delta = p[s];
    float2 bv = *(const float2*)(p + 64  + 2 * s);
    float2 cv = *(const float2*)(p + 192 + 2 * s);

    float Bm = 0.5f * (bv.x + bv.y);
    float Cm = 0.5f * (cv.x + cv.y);

    float A = -expf(Alog[s]);
    float sp = fmaxf(delta, 0.f) + log1pf(expf(-fabsf(delta)));
    float dA = sp * A;
    float Abar = expf(dA);

    float scale;
    if (fabsf(A) < 1e-4f) {
        scale = 1.f + dA * 0.5f + dA * dA * (1.f / 6.f);
    } else {
        scale = (Abar - 1.f) / A;
    }

    g_Abar[idx] = Abar;
    g_Bbar[idx] = scale * Bm;
    g_Cm[idx]   = Cm;
}

// ---------------------------------------------------------------------------
// 4. Chunked linear-recurrence scan
// ---------------------------------------------------------------------------
__global__ void scanA_kernel()
{
    int b = blockIdx.x / NCHUNK;
    int c = blockIdx.x % NCHUNK;
    int s = threadIdx.x;
    size_t base = ((size_t)b * SEQ + (size_t)c * CLEN) * DSTATE + s;
    float h = 0.f, p = 1.f;
    #pragma unroll 4
    for (int i = 0; i < CLEN; i++) {
        float a  = g_Abar[base + (size_t)i * DSTATE];
        float bb = g_Bbar[base + (size_t)i * DSTATE];
        h = fmaf(a, h, bb);
        p *= a;
    }
    int o = (b * NCHUNK + c) * DSTATE + s;
    g_P[o] = p;
    g_H[o] = h;
}

__global__ void scanB_kernel()
{
    int b = blockIdx.x;
    int s = threadIdx.x;
    int base = b * NCHUNK * DSTATE + s;
    float h  = 0.f;
    float pc = g_P[base];
    float hc = g_H[base];
    for (int c = 0; c < NCHUNK; c++) {
        float pn = 0.f, hn = 0.f;
        if (c + 1 < NCHUNK) {
            pn = g_P[base + (c + 1) * DSTATE];
            hn = g_H[base + (c + 1) * DSTATE];
        }
        g_Hin[base + c * DSTATE] = h;
        h  = fmaf(pc, h, hc);
        pc = pn; hc = hn;
    }
}

__global__ void scanC_kernel()
{
    int b = blockIdx.x / NCHUNK;
    int c = blockIdx.x % NCHUNK;
    int s = threadIdx.x;
    float h = g_Hin[(b * NCHUNK + c) * DSTATE + s];
    size_t base = ((size_t)b * SEQ + (size_t)c * CLEN) * DSTATE + s;
    #pragma unroll 4
    for (int i = 0; i < CLEN; i++) {
        float a  = g_Abar[base + (size_t)i * DSTATE];
        float bb = g_Bbar[base + (size_t)i * DSTATE];
        h = fmaf(a, h, bb);
        float yv = g_Cm[base + (size_t)i * DSTATE] * h;
        __nv_bfloat16 hi = __float2bfloat16(yv);
        g_yh[base + (size_t)i * DSTATE] = hi;
        g_yl[base + (size_t)i * DSTATE] = __float2bfloat16(yv - __bfloat162float(hi));
    }
}

// ---------------------------------------------------------------------------
// Launch
// ---------------------------------------------------------------------------
extern "C" void kernel_launch(void* const* d_in, const int* in_sizes, int n_in,
                              void* d_out, int out_size)
{
    (void)in_sizes; (void)n_in; (void)out_size;
    const float* x    = (const float*)d_in[0];
    const float* cw   = (const float*)d_in[1];
    const float* cb   = (const float*)d_in[2];
    const float* w1   = (const float*)d_in[3];
    const float* b1   = (const float*)d_in[4];
    const float* alog = (const float*)d_in[5];
    const float* w2   = (const float*)d_in[6];
    const float* b2   = (const float*)d_in[7];
    float* out = (float*)d_out;

    __nv_bfloat16 *w1h_p, *w1l_p, *w2h_p, *w2l_p;
    cudaGetSymbolAddress((void**)&w1h_p, g_w1h);
    cudaGetSymbolAddress((void**)&w1l_p, g_w1l);
    cudaGetSymbolAddress((void**)&w2h_p, g_w2h);
    cudaGetSymbolAddress((void**)&w2l_p, g_w2l);

    cudaFuncSetAttribute(gemm1_mma, cudaFuncAttributeMaxDynamicSharedMemorySize, G1_SMEM);
    cudaFuncSetAttribute(gemm2_mma, cudaFuncAttributeMaxDynamicSharedMemorySize, G2_SMEM);

    // 1. conv (split bf16 out) + weight splits
    {
        int n = BATCH * SEQ * (DMODEL / 4);
        conv_kernel<<<(n + 255) / 256, 256>>>(x, cw, cb);
        int n1 = NPROJ * DMODEL;
        wsplit_kernel<<<(n1 + 255) / 256, 256>>>(w1, w1h_p, w1l_p, n1);
        int n2 = DMODEL * DSTATE;
        wsplit_kernel<<<(n2 + 255) / 256, 256>>>(w2, w2h_p, w2l_p, n2);
    }
    // 2. proj = xc @ W1^T + b1  (tensor cores, split bf16)
    {
        dim3 grid(NPROJ / 160, M_ROWS / 128);
        gemm1_mma<<<grid, 256, G1_SMEM>>>(b1);
    }
    // 3. elementwise SSM params
    {
        int n = M_ROWS * DSTATE;
        elem_kernel<<<(n + 255) / 256, 256>>>(alog);
    }
    // 4. chunked scan (scanC emits split-bf16 y)
    scanA_kernel<<<BATCH * NCHUNK, DSTATE>>>();
    scanB_kernel<<<BATCH, DSTATE>>>();
    scanC_kernel<<<BATCH * NCHUNK, DSTATE>>>();

    // 5. out = y @ W2^T + b2  (tensor cores, split bf16)
    {
        dim3 grid(DMODEL / 128, M_ROWS / 128);
        gemm2_mma<<<grid, 256, G2_SMEM>>>(b2, out);
    }
}

// round 4
// speedup vs baseline: 1.9061x; 1.0793x over previous
#include <cuda_runtime.h>
#include <cuda_bf16.h>
#include <math.h>
#include <stdint.h>

// Problem constants (fixed by the reference)
#define BATCH   8
#define SEQ     4096
#define DMODEL  1024
#define DSTATE  64
#define NPROJ   320          // D_STATE + 2*INNER = 64 + 256
#define NCHUNK  64
#define CLEN    64           // SEQ / NCHUNK
#define M_ROWS  (BATCH*SEQ)  // 32768

// ---------------------------------------------------------------------------
// Scratch (static __device__ globals; no allocation in kernel_launch)
// ---------------------------------------------------------------------------
__device__ __nv_bfloat16 g_xch[(size_t)M_ROWS * DMODEL];  // conv out, hi bf16
__device__ __nv_bfloat16 g_xcl[(size_t)M_ROWS * DMODEL];  // conv out, lo bf16
__device__ __nv_bfloat16 g_w1h[(size_t)NPROJ * DMODEL];
__device__ __nv_bfloat16 g_w1l[(size_t)NPROJ * DMODEL];
__device__ __nv_bfloat16 g_w2h[(size_t)DMODEL * DSTATE];
__device__ __nv_bfloat16 g_w2l[(size_t)DMODEL * DSTATE];
__device__ __nv_bfloat16 g_yh [(size_t)M_ROWS * DSTATE];
__device__ __nv_bfloat16 g_yl [(size_t)M_ROWS * DSTATE];
__device__ float g_proj[(size_t)M_ROWS * NPROJ];    // in_proj output, 42 MB
__device__ float g_Abar[(size_t)M_ROWS * DSTATE];
__device__ float g_Bbar[(size_t)M_ROWS * DSTATE];
__device__ float g_Cm  [(size_t)M_ROWS * DSTATE];
__device__ float g_P   [BATCH * NCHUNK * DSTATE];
__device__ float g_H   [BATCH * NCHUNK * DSTATE];
__device__ float g_Hin [BATCH * NCHUNK * DSTATE];

// ---------------------------------------------------------------------------
// PTX helpers (legacy tensor path: ldmatrix + mma.sync, valid on sm_100 base)
// ---------------------------------------------------------------------------
__device__ __forceinline__ uint32_t smem_u32(const void* p) {
    uint32_t a;
    asm("{ .reg .u64 t; cvta.to.shared.u64 t, %1; cvt.u32.u64 %0, t; }" : "=r"(a) : "l"(p));
    return a;
}
__device__ __forceinline__ void ldsm_x4(uint32_t* r, uint32_t addr) {
    asm volatile("ldmatrix.sync.aligned.m8n8.x4.shared.b16 {%0,%1,%2,%3}, [%4];"
        : "=r"(r[0]), "=r"(r[1]), "=r"(r[2]), "=r"(r[3]) : "r"(addr));
}
__device__ __forceinline__ void ldsm_x2(uint32_t* r, uint32_t addr) {
    asm volatile("ldmatrix.sync.aligned.m8n8.x2.shared.b16 {%0,%1}, [%2];"
        : "=r"(r[0]), "=r"(r[1]) : "r"(addr));
}
__device__ __forceinline__ void mma_bf16(float* d, const uint32_t* a, const uint32_t* b) {
    asm volatile("mma.sync.aligned.m16n8k16.row.col.f32.bf16.bf16.f32 "
        "{%0,%1,%2,%3}, {%4,%5,%6,%7}, {%8,%9}, {%0,%1,%2,%3};"
        : "+f"(d[0]), "+f"(d[1]), "+f"(d[2]), "+f"(d[3])
        : "r"(a[0]), "r"(a[1]), "r"(a[2]), "r"(a[3]), "r"(b[0]), "r"(b[1]));
}
__device__ __forceinline__ void cp16(uint32_t saddr, const void* gaddr) {
    asm volatile("cp.async.cg.shared.global [%0], [%1], 16;" :: "r"(saddr), "l"(gaddr) : "memory");
}
#define CP_COMMIT()  asm volatile("cp.async.commit_group;" ::: "memory")
#define CP_WAIT(n)   asm volatile("cp.async.wait_group %0;" :: "n"(n) : "memory")
// SW128 swizzle on byte offsets (rows of 128 bytes)
#define SWZ(off) ((uint32_t)(off) ^ ((((uint32_t)(off)) >> 3) & 0x70))

// ---------------------------------------------------------------------------
// 1. Depthwise conv (k=4, pad=(1,1)), last timestep zeroed.
//    Emits split-bf16 (hi, lo) directly for the tensor-core GEMM.
// ---------------------------------------------------------------------------
__global__ void conv_kernel(const float* __restrict__ x,
                            const float* __restrict__ cw,
                            const float* __restrict__ cb)
{
    const int D4  = DMODEL / 4;
    int idx = blockIdx.x * blockDim.x + threadIdx.x;
    if (idx >= BATCH * SEQ * D4) return;

    int d4 = idx % D4;
    int bt = idx / D4;
    int t  = bt % SEQ;
    int b  = bt / SEQ;
    int d  = d4 * 4;

    float4 acc;
    if (t == SEQ - 1) {
        acc = make_float4(0.f, 0.f, 0.f, 0.f);
    } else {
        acc = *(const float4*)(cb + d);
        float4 w0 = *(const float4*)(cw + (size_t)(d + 0) * 4);
        float4 w1 = *(const float4*)(cw + (size_t)(d + 1) * 4);
        float4 w2 = *(const float4*)(cw + (size_t)(d + 2) * 4);
        float4 w3 = *(const float4*)(cw + (size_t)(d + 3) * 4);
        const float* wa0 = (const float*)&w0;
        const float* wa1 = (const float*)&w1;
        const float* wa2 = (const float*)&w2;
        const float* wa3 = (const float*)&w3;
        const float* xb = x + (size_t)b * SEQ * DMODEL + d;
        #pragma unroll
        for (int j = 0; j < 4; j++) {
            int tt = t - 1 + j;
            if (tt < 0 || tt >= SEQ) continue;
            float4 xv = *(const float4*)(xb + (size_t)tt * DMODEL);
            acc.x = fmaf(wa0[j], xv.x, acc.x);
            acc.y = fmaf(wa1[j], xv.y, acc.y);
            acc.z = fmaf(wa2[j], xv.z, acc.z);
            acc.w = fmaf(wa3[j], xv.w, acc.w);
        }
    }
    const float* a = (const float*)&acc;
    __nv_bfloat16 hi[4], lo[4];
    #pragma unroll
    for (int j = 0; j < 4; j++) {
        hi[j] = __float2bfloat16(a[j]);
        lo[j] = __float2bfloat16(a[j] - __bfloat162float(hi[j]));
    }
    size_t off = (size_t)bt * DMODEL + d;
    *(uint2*)(g_xch + off) = *(const uint2*)hi;
    *(uint2*)(g_xcl + off) = *(const uint2*)lo;
}

// ---------------------------------------------------------------------------
// 1b. Split weights into bf16 hi/lo
// ---------------------------------------------------------------------------
__global__ void wsplit_kernel(const float* __restrict__ w,
                              __nv_bfloat16* __restrict__ oh,
                              __nv_bfloat16* __restrict__ ol, int n)
{
    int i = blockIdx.x * blockDim.x + threadIdx.x;
    if (i >= n) return;
    float v = w[i];
    __nv_bfloat16 hi = __float2bfloat16(v);
    oh[i] = hi;
    ol[i] = __float2bfloat16(v - __bfloat162float(hi));
}

// ---------------------------------------------------------------------------
// 2. GEMM1 via mma.sync (split bf16, 3 passes), 3-stage cp.async pipeline:
//    proj[M,320] = xc[M,1024] @ W1[320,1024]^T + b1
//    CTA tile 128x160, K chunks of 64. 8 warps (2m x 4n), warp tile 64x40.
// ---------------------------------------------------------------------------
#define G1_AH 0
#define G1_AL 16384
#define G1_BH 32768
#define G1_BL 53248
#define G1_STAGE 73728
#define G1_NSTAGE 3
#define G1_SMEM (G1_STAGE * G1_NSTAGE)   // 221184 bytes

__global__ __launch_bounds__(256)
void gemm1_mma(const float* __restrict__ bias)
{
    extern __shared__ char smem[];
    const uint32_t sb = smem_u32(smem);
    const int tid  = threadIdx.x;
    const int lane = tid & 31;
    const int wid  = tid >> 5;
    const int wm   = (wid >> 2) * 64;   // 0 / 64
    const int wn   = (wid & 3) * 40;    // 0..120
    const int bm   = blockIdx.y * 128;
    const int bn   = blockIdx.x * 160;

    float d[4][5][4];
    #pragma unroll
    for (int i = 0; i < 4; i++)
        #pragma unroll
        for (int j = 0; j < 5; j++)
            #pragma unroll
            for (int c = 0; c < 4; c++) d[i][j][c] = 0.f;

    // Tile loader for chunk `it` into stage `st`
    auto load_chunk = [&](int it, int st) {
        const int k0 = it * 64;
        const uint32_t s0 = sb + st * G1_STAGE;
        #pragma unroll
        for (int i = tid; i < 1024; i += 256) {
            int r = i >> 3, cB = (i & 7) << 4;
            size_t go = (size_t)(bm + r) * DMODEL + k0 + (cB >> 1);
            uint32_t so = SWZ(r * 128 + cB);
            cp16(s0 + G1_AH + so, g_xch + go);
            cp16(s0 + G1_AL + so, g_xcl + go);
        }
        #pragma unroll
        for (int i = tid; i < 1280; i += 256) {
            int r = i >> 3, cB = (i & 7) << 4;
            size_t go = (size_t)(bn + r) * DMODEL + k0 + (cB >> 1);
            uint32_t so = SWZ(r * 128 + cB);
            cp16(s0 + G1_BH + so, g_w1h + go);
            cp16(s0 + G1_BL + so, g_w1l + go);
        }
        CP_COMMIT();
    };

    load_chunk(0, 0);
    load_chunk(1, 1);

    for (int iter = 0; iter < 16; iter++) {
        if (iter + 2 < 16) { load_chunk(iter + 2, (iter + 2) % G1_NSTAGE); CP_WAIT(2); }
        else if (iter + 1 < 16) { CP_WAIT(1); }
        else { CP_WAIT(0); }
        __syncthreads();

        const uint32_t sA = sb + (iter % G1_NSTAGE) * G1_STAGE;
        #pragma unroll
        for (int ks = 0; ks < 4; ks++) {
            const int kb = ks * 32;     // byte col of this k16 step
            // B fragments (5 n8 atoms), hi and lo
            uint32_t bh[5][2], bl[5][2];
            {
                int mi  = lane >> 3;
                int row = wn + ((mi & 1) << 3) + (lane & 7);
                int col = kb + ((mi >> 1) << 4);
                uint32_t so = SWZ(row * 128 + col);
                uint32_t r4[4];
                ldsm_x4(r4, sA + G1_BH + so);
                bh[0][0] = r4[0]; bh[1][0] = r4[1]; bh[0][1] = r4[2]; bh[1][1] = r4[3];
                ldsm_x4(r4, sA + G1_BL + so);
                bl[0][0] = r4[0]; bl[1][0] = r4[1]; bl[0][1] = r4[2]; bl[1][1] = r4[3];

                uint32_t so2 = SWZ((row + 16) * 128 + col);
                ldsm_x4(r4, sA + G1_BH + so2);
                bh[2][0] = r4[0]; bh[3][0] = r4[1]; bh[2][1] = r4[2]; bh[3][1] = r4[3];
                ldsm_x4(r4, sA + G1_BL + so2);
                bl[2][0] = r4[0]; bl[3][0] = r4[1]; bl[2][1] = r4[2]; bl[3][1] = r4[3];
            }
            {
                int mi  = (lane >> 3) & 1;
                int row = wn + 32 + (lane & 7);
                int col = kb + (mi << 4);
                uint32_t so = SWZ(row * 128 + col);
                ldsm_x2(bh[4], sA + G1_BH + so);
                ldsm_x2(bl[4], sA + G1_BL + so);
            }
            // A atoms (4 m16), hi and lo; 3-pass accumulate
            #pragma unroll
            for (int i = 0; i < 4; i++) {
                int mi  = lane >> 3;
                int row = wm + i * 16 + ((mi & 1) << 3) + (lane & 7);
                int col = kb + ((mi >> 1) << 4);
                uint32_t so = SWZ(row * 128 + col);
                uint32_t ah[4], al[4];
                ldsm_x4(ah, sA + G1_AH + so);
                ldsm_x4(al, sA + G1_AL + so);
                #pragma unroll
                for (int j = 0; j < 5; j++) {
                    mma_bf16(d[i][j], ah, bh[j]);
                    mma_bf16(d[i][j], ah, bl[j]);
                    mma_bf16(d[i][j], al, bh[j]);
                }
            }
        }
        __syncthreads();
    }

    // Epilogue
    const int gid = lane >> 2, tig = lane & 3;
    #pragma unroll
    for (int i = 0; i < 4; i++) {
        int row0 = bm + wm + i * 16 + gid;
        #pragma unroll
        for (int j = 0; j < 5; j++) {
            int col = bn + wn + j * 8 + tig * 2;
            float b0 = bias[col], b1 = bias[col + 1];
            float2 v0 = make_float2(d[i][j][0] + b0, d[i][j][1] + b1);
            float2 v1 = make_float2(d[i][j][2] + b0, d[i][j][3] + b1);
            *(float2*)(g_proj + (size_t)row0 * NPROJ + col)       = v0;
            *(float2*)(g_proj + (size_t)(row0 + 8) * NPROJ + col) = v1;
        }
    }
}

// ---------------------------------------------------------------------------
// 2b. GEMM2 via mma.sync (split bf16, 3 passes):
//    out[M,1024] = y[M,64] @ W2[1024,64]^T + b2
//    CTA tile 128x128, K=64 in one shot. 8 warps (2m x 4n), warp tile 64x32.
// ---------------------------------------------------------------------------
#define G2_AH 0
#define G2_AL 16384
#define G2_BH 32768
#define G2_BL 49152
#define G2_SMEM 65536

__global__ __launch_bounds__(256)
void gemm2_mma(const float* __restrict__ bias, float* __restrict__ out)
{
    extern __shared__ char smem[];
    const uint32_t sb = smem_u32(smem);
    const int tid  = threadIdx.x;
    const int lane = tid & 31;
    const int wid  = tid >> 5;
    const int wm   = (wid >> 2) * 64;
    const int wn   = (wid & 3) * 32;
    const int bm   = blockIdx.y * 128;
    const int bn   = blockIdx.x * 128;

    float d[4][4][4];
    #pragma unroll
    for (int i = 0; i < 4; i++)
        #pragma unroll
        for (int j = 0; j < 4; j++)
            #pragma unroll
            for (int c = 0; c < 4; c++) d[i][j][c] = 0.f;

    // A tile: 128 rows x 128B (64 bf16), hi + lo
    #pragma unroll
    for (int i = tid; i < 1024; i += 256) {
        int r = i >> 3, cB = (i & 7) << 4;
        size_t go = (size_t)(bm + r) * DSTATE + (cB >> 1);
        uint32_t so = SWZ(r * 128 + cB);
        cp16(sb + G2_AH + so, g_yh + go);
        cp16(sb + G2_AL + so, g_yl + go);
    }
    // B tile: 128 rows x 128B
    #pragma unroll
    for (int i = tid; i < 1024; i += 256) {
        int r = i >> 3, cB = (i & 7) << 4;
        size_t go = (size_t)(bn + r) * DSTATE + (cB >> 1);
        uint32_t so = SWZ(r * 128 + cB);
        cp16(sb + G2_BH + so, g_w2h + go);
        cp16(sb + G2_BL + so, g_w2l + go);
    }
    CP_COMMIT();
    CP_WAIT(0);
    __syncthreads();

    #pragma unroll
    for (int ks = 0; ks < 4; ks++) {
        const int kb = ks * 32;
        uint32_t bh[4][2], bl[4][2];
        {
            int mi  = lane >> 3;
            int row = wn + ((mi & 1) << 3) + (lane & 7);
            int col = kb + ((mi >> 1) << 4);
            uint32_t so = SWZ(row * 128 + col);
            uint32_t r4[4];
            ldsm_x4(r4, sb + G2_BH + so);
            bh[0][0] = r4[0]; bh[1][0] = r4[1]; bh[0][1] = r4[2]; bh[1][1] = r4[3];
            ldsm_x4(r4, sb + G2_BL + so);
            bl[0][0] = r4[0]; bl[1][0] = r4[1]; bl[0][1] = r4[2]; bl[1][1] = r4[3];
            uint32_t so2 = SWZ((row + 16) * 128 + col);
            ldsm_x4(r4, sb + G2_BH + so2);
            bh[2][0] = r4[0]; bh[3][0] = r4[1]; bh[2][1] = r4[2]; bh[3][1] = r4[3];
            ldsm_x4(r4, sb + G2_BL + so2);
            bl[2][0] = r4[0]; bl[3][0] = r4[1]; bl[2][1] = r4[2]; bl[3][1] = r4[3];
        }
        #pragma unroll
        for (int i = 0; i < 4; i++) {
            int mi  = lane >> 3;
            int row = wm + i * 16 + ((mi & 1) << 3) + (lane & 7);
            int col = kb + ((mi >> 1) << 4);
            uint32_t so = SWZ(row * 128 + col);
            uint32_t ah[4], al[4];
            ldsm_x4(ah, sb + G2_AH + so);
            ldsm_x4(al, sb + G2_AL + so);
            #pragma unroll
            for (int j = 0; j < 4; j++) {
                mma_bf16(d[i][j], ah, bh[j]);
                mma_bf16(d[i][j], ah, bl[j]);
                mma_bf16(d[i][j], al, bh[j]);
            }
        }
    }

    const int gid = lane >> 2, tig = lane & 3;
    #pragma unroll
    for (int i = 0; i < 4; i++) {
        int row0 = bm + wm + i * 16 + gid;
        #pragma unroll
        for (int j = 0; j < 4; j++) {
            int col = bn + wn + j * 8 + tig * 2;
            float b0 = bias[col], b1 = bias[col + 1];
            float2 v0 = make_float2(d[i][j][0] + b0, d[i][j][1] + b1);
            float2 v1 = make_float2(d[i][j][2] + b0, d[i][j][3] + b1);
            *(float2*)(out + (size_t)row0 * DMODEL + col)       = v0;
            *(float2*)(out + (size_t)(row0 + 8) * DMODEL + col) = v1;
        }
    }
}

// ---------------------------------------------------------------------------
// 3. Elementwise SSM params
// ---------------------------------------------------------------------------
__global__ void elem_kernel(const float* __restrict__ Alog)
{
    int idx = blockIdx.x * blockDim.x + threadIdx.x;
    if (idx >= M_ROWS * DSTATE) return;
    int s  = idx % DSTATE;
    int bt = idx / DSTATE;

    const float* p = g_proj + (size_t)bt * NPROJ;
    float  delta = p[s];
    float2 bv = *(const float2*)(p + 64  + 2 * s);
    float2 cv = *(const float2*)(p + 192 + 2 * s);

    float Bm = 0.5f * (bv.x + bv.y);
    float Cm = 0.5f * (cv.x + cv.y);

    float A = -expf(Alog[s]);
    float sp = fmaxf(delta, 0.f) + log1pf(expf(-fabsf(delta)));
    float dA = sp * A;
    float Abar = expf(dA);

    float scale;
    if (fabsf(A) < 1e-4f) {
        scale = 1.f + dA * 0.5f + dA * dA * (1.f / 6.f);
    } else {
        scale = (Abar - 1.f) / A;
    }

    g_Abar[idx] = Abar;
    g_Bbar[idx] = scale * Bm;
    g_Cm[idx]   = Cm;
}

// ---------------------------------------------------------------------------
// 4. Chunked linear-recurrence scan
// ---------------------------------------------------------------------------
__global__ void scanA_kernel()
{
    int b = blockIdx.x / NCHUNK;
    int c = blockIdx.x % NCHUNK;
    int s = threadIdx.x;
    size_t base = ((size_t)b * SEQ + (size_t)c * CLEN) * DSTATE + s;
    float h = 0.f, p = 1.f;
    #pragma unroll 4
    for (int i = 0; i < CLEN; i++) {
        float a  = g_Abar[base + (size_t)i * DSTATE];
        float bb = g_Bbar[base + (size_t)i * DSTATE];
        h = fmaf(a, h, bb);
        p *= a;
    }
    int o = (b * NCHUNK + c) * DSTATE + s;
    g_P[o] = p;
    g_H[o] = h;
}

__global__ void scanB_kernel()
{
    int b = blockIdx.x;
    int s = threadIdx.x;
    int base = b * NCHUNK * DSTATE + s;
    float h  = 0.f;
    float pc = g_P[base];
    float hc = g_H[base];
    for (int c = 0; c < NCHUNK; c++) {
        float pn = 0.f, hn = 0.f;
        if (c + 1 < NCHUNK) {
            pn = g_P[base + (c + 1) * DSTATE];
            hn = g_H[base + (c + 1) * DSTATE];
        }
        g_Hin[base + c * DSTATE] = h;
        h  = fmaf(pc, h, hc);
        pc = pn; hc = hn;
    }
}

__global__ void scanC_kernel()
{
    int b = blockIdx.x / NCHUNK;
    int c = blockIdx.x % NCHUNK;
    int s = threadIdx.x;
    float h = g_Hin[(b * NCHUNK + c) * DSTATE + s];
    size_t base = ((size_t)b * SEQ + (size_t)c * CLEN) * DSTATE + s;
    #pragma unroll 4
    for (int i = 0; i < CLEN; i++) {
        float a  = g_Abar[base + (size_t)i * DSTATE];
        float bb = g_Bbar[base + (size_t)i * DSTATE];
        h = fmaf(a, h, bb);
        float yv = g_Cm[base + (size_t)i * DSTATE] * h;
        __nv_bfloat16 hi = __float2bfloat16(yv);
        g_yh[base + (size_t)i * DSTATE] = hi;
        g_yl[base + (size_t)i * DSTATE] = __float2bfloat16(yv - __bfloat162float(hi));
    }
}

// ---------------------------------------------------------------------------
// Launch
// ---------------------------------------------------------------------------
extern "C" void kernel_launch(void* const* d_in, const int* in_sizes, int n_in,
                              void* d_out, int out_size)
{
    (void)in_sizes; (void)n_in; (void)out_size;
    const float* x    = (const float*)d_in[0];
    const float* cw   = (const float*)d_in[1];
    const float* cb   = (const float*)d_in[2];
    const float* w1   = (const float*)d_in[3];
    const float* b1   = (const float*)d_in[4];
    const float* alog = (const float*)d_in[5];
    const float* w2   = (const float*)d_in[6];
    const float* b2   = (const float*)d_in[7];
    float* out = (float*)d_out;

    __nv_bfloat16 *w1h_p, *w1l_p, *w2h_p, *w2l_p;
    cudaGetSymbolAddress((void**)&w1h_p, g_w1h);
    cudaGetSymbolAddress((void**)&w1l_p, g_w1l);
    cudaGetSymbolAddress((void**)&w2h_p, g_w2h);
    cudaGetSymbolAddress((void**)&w2l_p, g_w2l);

    cudaFuncSetAttribute(gemm1_mma, cudaFuncAttributeMaxDynamicSharedMemorySize, G1_SMEM);
    cudaFuncSetAttribute(gemm2_mma, cudaFuncAttributeMaxDynamicSharedMemorySize, G2_SMEM);

    // 1. conv (split bf16 out) + weight splits
    {
        int n = BATCH * SEQ * (DMODEL / 4);
        conv_kernel<<<(n + 255) / 256, 256>>>(x, cw, cb);
        int n1 = NPROJ * DMODEL;
        wsplit_kernel<<<(n1 + 255) / 256, 256>>>(w1, w1h_p, w1l_p, n1);
        int n2 = DMODEL * DSTATE;
        wsplit_kernel<<<(n2 + 255) / 256, 256>>>(w2, w2h_p, w2l_p, n2);
    }
    // 2. proj = xc @ W1^T + b1  (tensor cores, split bf16, pipelined)
    {
        dim3 grid(NPROJ / 160, M_ROWS / 128);
        gemm1_mma<<<grid, 256, G1_SMEM>>>(b1);
    }
    // 3. elementwise SSM params
    {
        int n = M_ROWS * DSTATE;
        elem_kernel<<<(n + 255) / 256, 256>>>(alog);
    }
    // 4. chunked scan (scanC emits split-bf16 y)
    scanA_kernel<<<BATCH * NCHUNK, DSTATE>>>();
    scanB_kernel<<<BATCH, DSTATE>>>();
    scanC_kernel<<<BATCH * NCHUNK, DSTATE>>>();

    // 5. out = y @ W2^T + b2  (tensor cores, split bf16)
    {
        dim3 grid(DMODEL / 128, M_ROWS / 128);
        gemm2_mma<<<grid, 256, G2_SMEM>>>(b2, out);
    }
}